// round 4
// baseline (speedup 1.0000x reference)
#include <cuda_runtime.h>
#include <cuda_bf16.h>

#define NN 50000
#define EE 800000
#define FI 128
#define HH 128
#define GG 256
#define TT 4

// ---------------- scratch (device globals; float4-typed => 16B alignment) ----------------
__device__ int    g_deg[NN];
__device__ int    g_rowptr[NN + 1];
__device__ int    g_pos[NN];
__device__ int    g_col[EE];
__device__ float  g_dinv[NN];
__device__ float4 g_ts[NN * 32];     // scaled transform ts = dinv * (X @ W), 128 floats/node
__device__ float4 g_h[NN * 32];      // layer activations
__device__ float  g_pooled[GG * HH];

// ---------------- degree histogram ----------------
__global__ void k_zero_deg() {
    int i = blockIdx.x * blockDim.x + threadIdx.x;
    if (i < NN) g_deg[i] = 0;
}

// NOTE: edge_index is int32 (JAX default x64-disabled downcasts jnp.int64 -> int32)
__global__ void k_hist(const int* __restrict__ ei) {
    int e = blockIdx.x * blockDim.x + threadIdx.x;
    if (e < EE) {
        int d = ei[EE + e];   // dst row
        atomicAdd(&g_deg[d], 1);
    }
}

// single-block scan over NN counts -> rowptr (exclusive), pos copy, dinv
__global__ void k_scan() {
    __shared__ int wsum[32];
    __shared__ int carry_sh;
    int tid = threadIdx.x, lane = tid & 31, wid = tid >> 5;
    if (tid == 0) carry_sh = 0;
    __syncthreads();
    for (int base = 0; base < NN; base += 1024) {
        int i = base + tid;
        int v = (i < NN) ? g_deg[i] : 0;
        int incl = v;
        #pragma unroll
        for (int o = 1; o < 32; o <<= 1) {
            int t = __shfl_up_sync(0xffffffffu, incl, o);
            if (lane >= o) incl += t;
        }
        if (lane == 31) wsum[wid] = incl;
        __syncthreads();
        if (wid == 0) {
            int s = wsum[lane];
            int si = s;
            #pragma unroll
            for (int o = 1; o < 32; o <<= 1) {
                int t = __shfl_up_sync(0xffffffffu, si, o);
                if (lane >= o) si += t;
            }
            wsum[lane] = si - s;   // exclusive warp offset
        }
        __syncthreads();
        int excl = carry_sh + wsum[wid] + incl - v;
        if (i < NN) {
            g_rowptr[i] = excl;
            g_pos[i]    = excl;
            g_dinv[i]   = rsqrtf((float)(v + 1));   // +1 self-loop
        }
        __syncthreads();
        if (tid == 1023) carry_sh += wsum[31] + incl;  // chunk total
        __syncthreads();
    }
    if (threadIdx.x == 0) g_rowptr[NN] = carry_sh;
}

__global__ void k_fill(const int* __restrict__ ei) {
    int e = blockIdx.x * blockDim.x + threadIdx.x;
    if (e < EE) {
        int d = ei[EE + e];
        int s = ei[e];
        int p = atomicAdd(&g_pos[d], 1);
        g_col[p] = s;
    }
}

// ---------------- GEMM: g_ts = dinv[i] * (X[i,:] @ W), X:[NN,128], W:[128,128] ----------------
// block = 64 rows x 128 cols, 256 threads. X tile in float4 smem (32KB),
// W streamed from global (each per-k warp read = one 512B line, L1-resident).
template <int SEL>
__global__ void k_gemm(const float4* __restrict__ Xin, const float4* __restrict__ W4) {
    __shared__ float4 Xs4[64 * 32];
    const float4* X4 = SEL ? (const float4*)g_h : Xin;
    int tid  = threadIdx.x;
    int row0 = blockIdx.x * 64;

    #pragma unroll
    for (int j = 0; j < 8; j++) {
        int fi = tid + j * 256;           // 0..2047 float4
        int r  = fi >> 5;                 // row 0..63
        int kq = fi & 31;                 // k-quad
        int gr = row0 + r;
        float4 v = make_float4(0.f, 0.f, 0.f, 0.f);
        if (gr < NN) v = X4[gr * 32 + kq];
        Xs4[fi] = v;
    }
    __syncthreads();

    int tx = tid & 31;   // col quad (cols tx*4..tx*4+3)
    int ty = tid >> 5;   // row group (rows ty*8..ty*8+7)
    float acc[8][4];
    #pragma unroll
    for (int i = 0; i < 8; i++)
        #pragma unroll
        for (int c = 0; c < 4; c++) acc[i][c] = 0.f;

    const float* Xsf = (const float*)Xs4;
    #pragma unroll 4
    for (int k = 0; k < 128; k++) {
        float4 wv = W4[k * 32 + tx];
        #pragma unroll
        for (int i = 0; i < 8; i++) {
            float xv = Xsf[(ty * 8 + i) * 128 + k];
            acc[i][0] = fmaf(xv, wv.x, acc[i][0]);
            acc[i][1] = fmaf(xv, wv.y, acc[i][1]);
            acc[i][2] = fmaf(xv, wv.z, acc[i][2]);
            acc[i][3] = fmaf(xv, wv.w, acc[i][3]);
        }
    }

    #pragma unroll
    for (int i = 0; i < 8; i++) {
        int gr = row0 + ty * 8 + i;
        if (gr < NN) {
            float di = g_dinv[gr];
            float4 o;
            o.x = acc[i][0] * di; o.y = acc[i][1] * di;
            o.z = acc[i][2] * di; o.w = acc[i][3] * di;
            g_ts[gr * 32 + tx] = o;
        }
    }
}

// ---------------- aggregation: g_h[i] = relu(dinv[i]*(sum ts[src] + ts[i]) + b) ----------------
// one warp per node, one float4 per lane (128 features)
__global__ void k_agg(const float4* __restrict__ b4) {
    int gtid = blockIdx.x * blockDim.x + threadIdx.x;
    int node = gtid >> 5;
    int lane = threadIdx.x & 31;
    if (node >= NN) return;
    float4 acc = g_ts[node * 32 + lane];   // self term (ts already dinv-scaled)
    int s = g_rowptr[node], e = g_rowptr[node + 1];
    int j = s;
    for (; j + 3 < e; j += 4) {
        int c0 = g_col[j], c1 = g_col[j + 1], c2 = g_col[j + 2], c3 = g_col[j + 3];
        float4 v0 = g_ts[c0 * 32 + lane];
        float4 v1 = g_ts[c1 * 32 + lane];
        float4 v2 = g_ts[c2 * 32 + lane];
        float4 v3 = g_ts[c3 * 32 + lane];
        acc.x += v0.x + v1.x + v2.x + v3.x;
        acc.y += v0.y + v1.y + v2.y + v3.y;
        acc.z += v0.z + v1.z + v2.z + v3.z;
        acc.w += v0.w + v1.w + v2.w + v3.w;
    }
    for (; j < e; j++) {
        int c = g_col[j];
        float4 v = g_ts[c * 32 + lane];
        acc.x += v.x; acc.y += v.y; acc.z += v.z; acc.w += v.w;
    }
    float di = g_dinv[node];
    float4 bb = b4[lane];
    float4 o;
    o.x = fmaxf(fmaf(acc.x, di, bb.x), 0.f);
    o.y = fmaxf(fmaf(acc.y, di, bb.y), 0.f);
    o.z = fmaxf(fmaf(acc.z, di, bb.z), 0.f);
    o.w = fmaxf(fmaf(acc.w, di, bb.w), 0.f);
    g_h[node * 32 + lane] = o;
}

// ---------------- mean pool per graph (batch sorted, int32 -> binary search bounds) --------
__device__ __forceinline__ int lb_batch(const int* b, int v) {
    int lo = 0, hi = NN;
    while (lo < hi) {
        int m = (lo + hi) >> 1;
        if (b[m] < v) lo = m + 1; else hi = m;
    }
    return lo;
}

__global__ void k_pool(const int* __restrict__ batch) {
    int g = blockIdx.x;        // 0..255
    int tid = threadIdx.x;     // 0..127
    __shared__ int s0, s1;
    if (tid == 0) {
        s0 = lb_batch(batch, g);
        s1 = lb_batch(batch, g + 1);
    }
    __syncthreads();
    int a = s0, bnd = s1;
    const float* h = (const float*)g_h;
    float acc = 0.f;
    int n = a;
    for (; n + 3 < bnd; n += 4) {
        acc += h[n * 128 + tid] + h[(n + 1) * 128 + tid]
             + h[(n + 2) * 128 + tid] + h[(n + 3) * 128 + tid];
    }
    for (; n < bnd; n++) acc += h[n * 128 + tid];
    float cnt = (float)(bnd - a);
    g_pooled[g * 128 + tid] = acc / fmaxf(cnt, 1.f);
}

// ---------------- head: z = relu(pooled @ Wfc + bfc); out[t,g,c] = z . Wh[t,:,c] + bh ------
__global__ void k_head(const float* __restrict__ Wfc, const float* __restrict__ bfc,
                       const float* __restrict__ Wh, const float* __restrict__ bh,
                       float* __restrict__ out) {
    int g = blockIdx.x;
    int tid = threadIdx.x;   // 0..127
    __shared__ float pr[128];
    __shared__ float zs[128];
    pr[tid] = g_pooled[g * 128 + tid];
    __syncthreads();
    float acc = bfc[tid];
    #pragma unroll 4
    for (int h = 0; h < 128; h++) acc = fmaf(pr[h], Wfc[h * 128 + tid], acc);
    zs[tid] = fmaxf(acc, 0.f);
    __syncthreads();
    if (tid < TT * 2) {
        int t = tid >> 1, c = tid & 1;
        float s = bh[t * 2 + c];
        #pragma unroll 4
        for (int h = 0; h < 128; h++) s = fmaf(zs[h], Wh[t * 256 + h * 2 + c], s);
        out[t * (GG * 2) + g * 2 + c] = s;
    }
}

// ---------------- launch (kernel launches ONLY — graph-capture safe) ----------------
extern "C" void kernel_launch(void* const* d_in, const int* in_sizes, int n_in,
                              void* d_out, int out_size) {
    const float* x     = (const float*)d_in[0];
    const int*   ei    = (const int*)d_in[1];     // int32 (JAX x64 disabled)
    const int*   batch = (const int*)d_in[2];     // int32
    const float* W1    = (const float*)d_in[3];
    const float* b1    = (const float*)d_in[4];
    const float* W2    = (const float*)d_in[5];
    const float* b2    = (const float*)d_in[6];
    const float* Wfc   = (const float*)d_in[7];
    const float* bfc   = (const float*)d_in[8];
    const float* Wh    = (const float*)d_in[9];
    const float* bh    = (const float*)d_in[10];
    float* out = (float*)d_out;

    // CSR + degrees
    k_zero_deg<<<(NN + 255) / 256, 256>>>();
    k_hist<<<(EE + 255) / 256, 256>>>(ei);
    k_scan<<<1, 1024>>>();
    k_fill<<<(EE + 255) / 256, 256>>>(ei);

    int gemm_blocks = (NN + 63) / 64;
    int agg_blocks  = (NN * 32 + 255) / 256;

    // layer 1
    k_gemm<0><<<gemm_blocks, 256>>>((const float4*)x, (const float4*)W1);
    k_agg<<<agg_blocks, 256>>>((const float4*)b1);
    // layer 2
    k_gemm<1><<<gemm_blocks, 256>>>((const float4*)x, (const float4*)W2);
    k_agg<<<agg_blocks, 256>>>((const float4*)b2);
    // pool + head
    k_pool<<<GG, 128>>>(batch);
    k_head<<<GG, 128>>>(Wfc, bfc, Wh, bh, out);
}